// round 2
// baseline (speedup 1.0000x reference)
#include <cuda_runtime.h>
#include <math.h>

#define Nn 20000
#define Ee 160000
#define FIN 30
#define EDIM 11
#define HH 4
#define CC 128
#define HC 512
#define EMB 128
#define GG 1000

// ---------------- scratch (device globals; no allocation) ----------------
__device__ float g_xs[Nn * HC];        // transformed nodes per layer
__device__ float g_out[Nn * HC];       // aggregated output per layer
__device__ float g_h[Nn * EMB];        // layer input (layers 1..3) / BN output
__device__ float g_h2[Nn * EMB];       // head-transform output (pre-BN)
__device__ float g_asrcn[Nn * HH];     // per-node src attention logits
__device__ float g_adstn[Nn * HH];     // per-node dst attention logits
__device__ float g_eatt[Ee * 16];      // per-edge attention logits [E][layer][head]
__device__ float g_vtab[4 * EDIM * HH];
__device__ int   g_deg[Nn];
__device__ int   g_rowptr[Nn + 1];
__device__ int   g_cursor[Nn];
__device__ int   g_csrsrc[Ee];
__device__ int   g_csreid[Ee];
__device__ float g_bnsum[EMB];
__device__ float g_bnsq[EMB];
__device__ int   g_gs[GG];
__device__ int   g_ge[GG];

// ---------------- small utility kernels ----------------
__global__ void zero_i_kernel(int* p, int n) {
    int i = blockIdx.x * blockDim.x + threadIdx.x;
    if (i < n) p[i] = 0;
}
__global__ void zero_bn_kernel() {
    int i = threadIdx.x;
    if (i < EMB) { g_bnsum[i] = 0.f; g_bnsq[i] = 0.f; }
}

// ---------------- CSR build ----------------
__global__ void deg_kernel(const int* __restrict__ dst) {
    int e = blockIdx.x * blockDim.x + threadIdx.x;
    if (e < Ee) atomicAdd(&g_deg[dst[e]], 1);
}

__global__ void scan_kernel() {
    __shared__ int sh[1024];
    __shared__ int carry;
    int t = threadIdx.x;
    if (t == 0) carry = 0;
    __syncthreads();
    for (int base = 0; base < Nn; base += 1024) {
        int v = (base + t < Nn) ? g_deg[base + t] : 0;
        sh[t] = v;
        __syncthreads();
        for (int d = 1; d < 1024; d <<= 1) {
            int x = (t >= d) ? sh[t - d] : 0;
            __syncthreads();
            sh[t] += x;
            __syncthreads();
        }
        int excl = carry + sh[t] - v;
        if (base + t < Nn) { g_rowptr[base + t] = excl; g_cursor[base + t] = excl; }
        __syncthreads();
        if (t == 0) carry += sh[1023];
        __syncthreads();
    }
    if (t == 0) g_rowptr[Nn] = carry;
}

__global__ void scatter_kernel(const int* __restrict__ src, const int* __restrict__ dst) {
    int e = blockIdx.x * blockDim.x + threadIdx.x;
    if (e >= Ee) return;
    int d = dst[e];
    int p = atomicAdd(&g_cursor[d], 1);
    g_csrsrc[p] = src[e];
    g_csreid[p] = e;
}

// ---------------- edge attention precompute ----------------
// v[L][d][h] = sum_c edge_w_L[d, h*C+c] * a_e_L[h, c]
__global__ void vtab_kernel(const float* __restrict__ g0_edge, const float* __restrict__ g_edge,
                            const float* __restrict__ g0_aedge, const float* __restrict__ g_aedge) {
    int idx = blockIdx.x;                 // L*44 + d*4 + h
    int L = idx / (EDIM * HH);
    int r = idx % (EDIM * HH);
    int d = r / HH, h = r % HH;
    const float* ew = (L == 0) ? g0_edge : g_edge + (size_t)(L - 1) * EDIM * HC;
    const float* ae = (L == 0) ? g0_aedge : g_aedge + (size_t)(L - 1) * HH * CC;
    int c = threadIdx.x;                  // 128 threads
    float p = ew[d * HC + h * CC + c] * ae[h * CC + c];
    // reduce 128 -> 1
    __shared__ float sw[4];
    for (int o = 16; o; o >>= 1) p += __shfl_xor_sync(0xffffffffu, p, o);
    if ((c & 31) == 0) sw[c >> 5] = p;
    __syncthreads();
    if (c == 0) g_vtab[idx] = sw[0] + sw[1] + sw[2] + sw[3];
}

__global__ void eatt_kernel(const float* __restrict__ ea) {
    __shared__ float v[4 * EDIM * HH];
    // FIX: 176 entries > 128 threads; must stride the load
    for (int i = threadIdx.x; i < 4 * EDIM * HH; i += blockDim.x) v[i] = g_vtab[i];
    __syncthreads();
    int e = blockIdx.x * blockDim.x + threadIdx.x;
    if (e >= Ee) return;
    float a[EDIM];
#pragma unroll
    for (int d = 0; d < EDIM; d++) a[d] = ea[(size_t)e * EDIM + d];
#pragma unroll
    for (int L = 0; L < 4; L++) {
#pragma unroll
        for (int h = 0; h < HH; h++) {
            float s = 0.f;
#pragma unroll
            for (int d = 0; d < EDIM; d++) s += a[d] * v[L * 44 + d * 4 + h];
            g_eatt[(size_t)e * 16 + L * 4 + h] = s;
        }
    }
}

// ---------------- GEMM: C[M,N] = A[M,K] @ B[K,N] (+bias) ----------------
#define BM 64
#define BN 64
#define BK 16
__global__ void gemm_kernel(const float* __restrict__ A, const float* __restrict__ B,
                            const float* __restrict__ bias, float* __restrict__ C,
                            int M, int N, int K) {
    __shared__ float sA[BK][BM];
    __shared__ float sB[BK][BN];
    int tx = threadIdx.x & 15, ty = threadIdx.x >> 4;   // 16x16 threads
    int rowBase = blockIdx.y * BM, colBase = blockIdx.x * BN;
    float acc[4][4];
#pragma unroll
    for (int m = 0; m < 4; m++)
#pragma unroll
        for (int n = 0; n < 4; n++) acc[m][n] = 0.f;

    for (int k0 = 0; k0 < K; k0 += BK) {
        for (int i = threadIdx.x; i < BM * BK; i += 256) {
            int r = i >> 4, kk = i & 15;
            int gr = rowBase + r, gk = k0 + kk;
            sA[kk][r] = (gr < M && gk < K) ? A[(size_t)gr * K + gk] : 0.f;
        }
        for (int i = threadIdx.x; i < BK * BN; i += 256) {
            int kk = i >> 6, c = i & 63;
            int gk = k0 + kk, gc = colBase + c;
            sB[kk][c] = (gk < K && gc < N) ? B[(size_t)gk * N + gc] : 0.f;
        }
        __syncthreads();
#pragma unroll
        for (int kk = 0; kk < BK; kk++) {
            float a[4], b[4];
#pragma unroll
            for (int m = 0; m < 4; m++) a[m] = sA[kk][ty * 4 + m];
#pragma unroll
            for (int n = 0; n < 4; n++) b[n] = sB[kk][tx * 4 + n];
#pragma unroll
            for (int m = 0; m < 4; m++)
#pragma unroll
                for (int n = 0; n < 4; n++) acc[m][n] += a[m] * b[n];
        }
        __syncthreads();
    }
#pragma unroll
    for (int m = 0; m < 4; m++) {
        int gr = rowBase + ty * 4 + m;
        if (gr >= M) continue;
#pragma unroll
        for (int n = 0; n < 4; n++) {
            int gc = colBase + tx * 4 + n;
            if (gc >= N) continue;
            float v = acc[m][n];
            if (bias) v += bias[gc];
            C[(size_t)gr * N + gc] = v;
        }
    }
}

// ---------------- per-node attention logits ----------------
__global__ void anode_kernel(const float* __restrict__ asrc, const float* __restrict__ adst) {
    int n = blockIdx.x;
    int w = threadIdx.x >> 5, lane = threadIdx.x & 31;  // 4 warps = 4 heads
    float s1 = 0.f, s2 = 0.f;
    const float* xr = &g_xs[(size_t)n * HC + w * CC];
#pragma unroll
    for (int c = lane; c < CC; c += 32) {
        float xv = xr[c];
        s1 += xv * asrc[w * CC + c];
        s2 += xv * adst[w * CC + c];
    }
    for (int o = 16; o; o >>= 1) {
        s1 += __shfl_xor_sync(0xffffffffu, s1, o);
        s2 += __shfl_xor_sync(0xffffffffu, s2, o);
    }
    if (lane == 0) { g_asrcn[n * HH + w] = s1; g_adstn[n * HH + w] = s2; }
}

// ---------------- softmax + aggregation: one warp per dst ----------------
__device__ __forceinline__ float lrelu(float a) { return a > 0.f ? a : 0.2f * a; }

__global__ void agg_kernel(int layer, const float* __restrict__ bias) {
    int gw = (blockIdx.x * blockDim.x + threadIdx.x) >> 5;
    int lane = threadIdx.x & 31;
    if (gw >= Nn) return;
    int n = gw;
    int beg = g_rowptr[n], end = g_rowptr[n + 1];
    int deg = end - beg;
    float4 ad = *(const float4*)&g_adstn[n * HH];

    // phase 1: max + edge-att sum (for self-loop mean)
    float m0 = -1e30f, m1 = -1e30f, m2 = -1e30f, m3 = -1e30f;
    float e0 = 0.f, e1 = 0.f, e2 = 0.f, e3 = 0.f;
    for (int j = beg + lane; j < end; j += 32) {
        int s = g_csrsrc[j], eid = g_csreid[j];
        float4 as = *(const float4*)&g_asrcn[s * HH];
        float4 ev = *(const float4*)&g_eatt[(size_t)eid * 16 + layer * 4];
        m0 = fmaxf(m0, lrelu(as.x + ad.x + ev.x)); e0 += ev.x;
        m1 = fmaxf(m1, lrelu(as.y + ad.y + ev.y)); e1 += ev.y;
        m2 = fmaxf(m2, lrelu(as.z + ad.z + ev.z)); e2 += ev.z;
        m3 = fmaxf(m3, lrelu(as.w + ad.w + ev.w)); e3 += ev.w;
    }
    for (int o = 16; o; o >>= 1) {
        m0 = fmaxf(m0, __shfl_xor_sync(0xffffffffu, m0, o));
        m1 = fmaxf(m1, __shfl_xor_sync(0xffffffffu, m1, o));
        m2 = fmaxf(m2, __shfl_xor_sync(0xffffffffu, m2, o));
        m3 = fmaxf(m3, __shfl_xor_sync(0xffffffffu, m3, o));
        e0 += __shfl_xor_sync(0xffffffffu, e0, o);
        e1 += __shfl_xor_sync(0xffffffffu, e1, o);
        e2 += __shfl_xor_sync(0xffffffffu, e2, o);
        e3 += __shfl_xor_sync(0xffffffffu, e3, o);
    }
    float4 asn = *(const float4*)&g_asrcn[n * HH];
    float invd = 1.f / fmaxf((float)deg, 1.f);
    float sa0 = lrelu(asn.x + ad.x + e0 * invd);
    float sa1 = lrelu(asn.y + ad.y + e1 * invd);
    float sa2 = lrelu(asn.z + ad.z + e2 * invd);
    float sa3 = lrelu(asn.w + ad.w + e3 * invd);
    m0 = fmaxf(m0, sa0); m1 = fmaxf(m1, sa1); m2 = fmaxf(m2, sa2); m3 = fmaxf(m3, sa3);

    // phase 2: denominators
    float d0 = 0.f, d1 = 0.f, d2 = 0.f, d3 = 0.f;
    for (int j = beg + lane; j < end; j += 32) {
        int s = g_csrsrc[j], eid = g_csreid[j];
        float4 as = *(const float4*)&g_asrcn[s * HH];
        float4 ev = *(const float4*)&g_eatt[(size_t)eid * 16 + layer * 4];
        d0 += expf(lrelu(as.x + ad.x + ev.x) - m0);
        d1 += expf(lrelu(as.y + ad.y + ev.y) - m1);
        d2 += expf(lrelu(as.z + ad.z + ev.z) - m2);
        d3 += expf(lrelu(as.w + ad.w + ev.w) - m3);
    }
    for (int o = 16; o; o >>= 1) {
        d0 += __shfl_xor_sync(0xffffffffu, d0, o);
        d1 += __shfl_xor_sync(0xffffffffu, d1, o);
        d2 += __shfl_xor_sync(0xffffffffu, d2, o);
        d3 += __shfl_xor_sync(0xffffffffu, d3, o);
    }
    float ws0 = expf(sa0 - m0), ws1 = expf(sa1 - m1), ws2 = expf(sa2 - m2), ws3 = expf(sa3 - m3);
    d0 += ws0; d1 += ws1; d2 += ws2; d3 += ws3;
    float id0 = 1.f / d0, id1 = 1.f / d1, id2 = 1.f / d2, id3 = 1.f / d3;
    ws0 *= id0; ws1 *= id1; ws2 *= id2; ws3 *= id3;

    // phase 3: weighted aggregation (512 channels per warp, 4 float4 per lane)
    const float4* xr = (const float4*)&g_xs[(size_t)n * HC];
    float4 x0 = xr[lane], x1 = xr[32 + lane], x2 = xr[64 + lane], x3 = xr[96 + lane];
    float4 a0, a1, a2, a3;
    a0.x = ws0 * x0.x; a0.y = ws0 * x0.y; a0.z = ws0 * x0.z; a0.w = ws0 * x0.w;
    a1.x = ws1 * x1.x; a1.y = ws1 * x1.y; a1.z = ws1 * x1.z; a1.w = ws1 * x1.w;
    a2.x = ws2 * x2.x; a2.y = ws2 * x2.y; a2.z = ws2 * x2.z; a2.w = ws2 * x2.w;
    a3.x = ws3 * x3.x; a3.y = ws3 * x3.y; a3.z = ws3 * x3.z; a3.w = ws3 * x3.w;

    for (int j = beg; j < end; j++) {
        int s = g_csrsrc[j], eid = g_csreid[j];
        float4 as = *(const float4*)&g_asrcn[s * HH];
        float4 ev = *(const float4*)&g_eatt[(size_t)eid * 16 + layer * 4];
        float w0 = expf(lrelu(as.x + ad.x + ev.x) - m0) * id0;
        float w1 = expf(lrelu(as.y + ad.y + ev.y) - m1) * id1;
        float w2 = expf(lrelu(as.z + ad.z + ev.z) - m2) * id2;
        float w3 = expf(lrelu(as.w + ad.w + ev.w) - m3) * id3;
        const float4* sr = (const float4*)&g_xs[(size_t)s * HC];
        float4 v0 = sr[lane], v1 = sr[32 + lane], v2 = sr[64 + lane], v3 = sr[96 + lane];
        a0.x += w0 * v0.x; a0.y += w0 * v0.y; a0.z += w0 * v0.z; a0.w += w0 * v0.w;
        a1.x += w1 * v1.x; a1.y += w1 * v1.y; a1.z += w1 * v1.z; a1.w += w1 * v1.w;
        a2.x += w2 * v2.x; a2.y += w2 * v2.y; a2.z += w2 * v2.z; a2.w += w2 * v2.w;
        a3.x += w3 * v3.x; a3.y += w3 * v3.y; a3.z += w3 * v3.z; a3.w += w3 * v3.w;
    }

    const float4* b4 = (const float4*)bias;
    float4 bb;
    float4* orow = (float4*)&g_out[(size_t)n * HC];
    bb = b4[lane];       a0.x += bb.x; a0.y += bb.y; a0.z += bb.z; a0.w += bb.w; orow[lane] = a0;
    bb = b4[32 + lane];  a1.x += bb.x; a1.y += bb.y; a1.z += bb.z; a1.w += bb.w; orow[32 + lane] = a1;
    bb = b4[64 + lane];  a2.x += bb.x; a2.y += bb.y; a2.z += bb.z; a2.w += bb.w; orow[64 + lane] = a2;
    bb = b4[96 + lane];  a3.x += bb.x; a3.y += bb.y; a3.z += bb.z; a3.w += bb.w; orow[96 + lane] = a3;
}

// ---------------- elementwise tanh ----------------
__global__ void tanh_kernel(float* __restrict__ p, int n) {
    int i = blockIdx.x * blockDim.x + threadIdx.x;
    if (i < n) p[i] = tanhf(p[i]);
}

// ---------------- batchnorm ----------------
__global__ void bn_stats_kernel() {
    int c = threadIdx.x;                 // 128
    int r0 = blockIdx.x * 128;
    int r1 = min(r0 + 128, Nn);
    float s = 0.f, q = 0.f;
    for (int r = r0; r < r1; r++) {
        float v = g_h2[(size_t)r * EMB + c];
        s += v; q += v * v;
    }
    atomicAdd(&g_bnsum[c], s);
    atomicAdd(&g_bnsq[c], q);
}

__global__ void bn_apply_kernel(const float* __restrict__ gamma, const float* __restrict__ beta) {
    int i = blockIdx.x * blockDim.x + threadIdx.x;
    if (i >= Nn * EMB) return;
    int c = i & (EMB - 1);
    float mu = g_bnsum[c] * (1.f / Nn);
    float var = g_bnsq[c] * (1.f / Nn) - mu * mu;
    g_h[i] = (g_h2[i] - mu) * rsqrtf(var + 1e-5f) * gamma[c] + beta[c];
}

// ---------------- pooling ----------------
__global__ void gb_init_kernel() {
    int g = blockIdx.x * blockDim.x + threadIdx.x;
    if (g < GG) { g_gs[g] = Nn; g_ge[g] = 0; }
}
__global__ void gb_bounds_kernel(const int* __restrict__ batch) {
    int n = blockIdx.x * blockDim.x + threadIdx.x;
    if (n >= Nn) return;
    int g = batch[n];
    atomicMin(&g_gs[g], n);
    atomicMax(&g_ge[g], n + 1);
}
__global__ void pool_kernel(float* __restrict__ d_out) {
    int g = blockIdx.x;
    int c = threadIdx.x;                 // 128
    int s = g_gs[g], e = g_ge[g];
    int cnt = (e > s) ? (e - s) : 0;
    float mx = -1e30f, sum = 0.f;
    for (int n = s; n < e; n++) {
        float v = g_h[(size_t)n * EMB + c];
        mx = fmaxf(mx, v);
        sum += v;
    }
    float* hid = d_out + GG + (size_t)g * 2 * EMB;
    hid[c] = (cnt > 0) ? mx : 0.f;
    hid[EMB + c] = (cnt > 0) ? sum / (float)cnt : 0.f;
}

// ---------------- readout MLP ----------------
__global__ void mlp_kernel(const float* __restrict__ w1, const float* __restrict__ b1,
                           const float* __restrict__ w2, const float* __restrict__ b2,
                           float* __restrict__ d_out) {
    __shared__ float hid[256];
    __shared__ float o[256];
    int g = blockIdx.x;
    int t = threadIdx.x;                 // 256
    hid[t] = d_out[GG + (size_t)g * 256 + t];
    __syncthreads();
    float s = b1[t];
#pragma unroll 8
    for (int k = 0; k < 256; k++) s += hid[k] * w1[(size_t)k * 256 + t];
    s = s > 0.f ? s : 0.f;
    o[t] = s * w2[t];
    __syncthreads();
    for (int d = 128; d; d >>= 1) {
        if (t < d) o[t] += o[t + d];
        __syncthreads();
    }
    if (t == 0) d_out[g] = o[0] + b2[0];
}

// ---------------- driver ----------------
static inline dim3 gemm_grid(int M, int N) {
    return dim3((N + BN - 1) / BN, (M + BM - 1) / BM);
}

extern "C" void kernel_launch(void* const* d_in, const int* in_sizes, int n_in,
                              void* d_out_v, int out_size) {
    const float* x         = (const float*)d_in[0];
    const int*   edge_idx  = (const int*)d_in[1];
    const float* edge_attr = (const float*)d_in[2];
    const int*   batch     = (const int*)d_in[3];
    const float* g0_lin    = (const float*)d_in[4];
    const float* g0_edge   = (const float*)d_in[5];
    const float* g0_asrc   = (const float*)d_in[6];
    const float* g0_adst   = (const float*)d_in[7];
    const float* g0_aedge  = (const float*)d_in[8];
    const float* g0_b      = (const float*)d_in[9];
    const float* g_lin     = (const float*)d_in[10];
    const float* g_edge    = (const float*)d_in[11];
    const float* g_asrc    = (const float*)d_in[12];
    const float* g_adst    = (const float*)d_in[13];
    const float* g_aedge   = (const float*)d_in[14];
    const float* g_b       = (const float*)d_in[15];
    const float* ht_w      = (const float*)d_in[16];
    const float* ht_b      = (const float*)d_in[17];
    const float* bn_g      = (const float*)d_in[18];
    const float* bn_b      = (const float*)d_in[19];
    const float* out1_w    = (const float*)d_in[20];
    const float* out1_b    = (const float*)d_in[21];
    const float* out2_w    = (const float*)d_in[22];
    const float* out2_b    = (const float*)d_in[23];
    float* d_out = (float*)d_out_v;

    const int* src = edge_idx;
    const int* dst = edge_idx + Ee;

    // CSR build (per call; deterministic work)
    int* degPtr = nullptr;
    cudaGetSymbolAddress((void**)&degPtr, g_deg);
    zero_i_kernel<<<(Nn + 255) / 256, 256>>>(degPtr, Nn);
    deg_kernel<<<(Ee + 255) / 256, 256>>>(dst);
    scan_kernel<<<1, 1024>>>();
    scatter_kernel<<<(Ee + 255) / 256, 256>>>(src, dst);

    // edge attention precompute for all 4 layers
    vtab_kernel<<<4 * EDIM * HH, 128>>>(g0_edge, g_edge, g0_aedge, g_aedge);
    eatt_kernel<<<(Ee + 127) / 128, 128>>>(edge_attr);

    float* xsPtr = nullptr;  cudaGetSymbolAddress((void**)&xsPtr, g_xs);
    float* outPtr = nullptr; cudaGetSymbolAddress((void**)&outPtr, g_out);
    float* hPtr = nullptr;   cudaGetSymbolAddress((void**)&hPtr, g_h);
    float* h2Ptr = nullptr;  cudaGetSymbolAddress((void**)&h2Ptr, g_h2);

    for (int L = 0; L < 4; L++) {
        const float* lin  = (L == 0) ? g0_lin  : g_lin  + (size_t)(L - 1) * EMB * HC;
        const float* as_  = (L == 0) ? g0_asrc : g_asrc + (size_t)(L - 1) * HH * CC;
        const float* ad_  = (L == 0) ? g0_adst : g_adst + (size_t)(L - 1) * HH * CC;
        const float* bia  = (L == 0) ? g0_b    : g_b    + (size_t)(L - 1) * HC;
        const float* hin  = (L == 0) ? x : hPtr;
        int K = (L == 0) ? FIN : EMB;

        // xs = h_in @ lin  [N, HC]
        gemm_kernel<<<gemm_grid(Nn, HC), 256>>>(hin, lin, nullptr, xsPtr, Nn, HC, K);
        // per-node attention logits
        anode_kernel<<<Nn, 128>>>(as_, ad_);
        // softmax + aggregation (+bias)
        agg_kernel<<<(Nn * 32 + 255) / 256, 256>>>(L, bia);
        // tanh in place
        tanh_kernel<<<(Nn * HC + 255) / 256, 256>>>(outPtr, Nn * HC);
        // head transform: h2 = tanh_out @ ht_w[L] + ht_b[L]
        gemm_kernel<<<gemm_grid(Nn, EMB), 256>>>(outPtr, ht_w + (size_t)L * HC * EMB,
                                                 ht_b + (size_t)L * EMB, h2Ptr, Nn, EMB, HC);
        // batchnorm -> g_h
        zero_bn_kernel<<<1, 128>>>();
        bn_stats_kernel<<<(Nn + 127) / 128, 128>>>();
        bn_apply_kernel<<<(Nn * EMB + 255) / 256, 256>>>(bn_g + (size_t)L * EMB, bn_b + (size_t)L * EMB);
    }

    // pooling + readout
    gb_init_kernel<<<(GG + 255) / 256, 256>>>();
    gb_bounds_kernel<<<(Nn + 255) / 256, 256>>>(batch);
    pool_kernel<<<GG, 128>>>(d_out);
    mlp_kernel<<<GG, 256>>>(out1_w, out1_b, out2_w, out2_b, d_out);
}

// round 3
// speedup vs baseline: 1.4124x; 1.4124x over previous
#include <cuda_runtime.h>
#include <math.h>

#define Nn 20000
#define Ee 160000
#define FIN 30
#define EDIM 11
#define HH 4
#define CC 128
#define HC 512
#define EMB 128
#define GG 1000

// ---------------- scratch (device globals; no allocation) ----------------
__device__ float g_xs[Nn * HC];        // transformed nodes per layer
__device__ float g_out[Nn * HC];       // aggregated output per layer
__device__ float g_h[Nn * EMB];        // layer input (layers 1..3) / BN output
__device__ float g_h2[Nn * EMB];       // head-transform output (pre-BN)
__device__ float g_asrcn[Nn * HH];     // per-node src attention logits
__device__ float g_adstn[Nn * HH];     // per-node dst attention logits
__device__ float g_eatt[Ee * 16];      // per-edge attention logits [E][layer][head]
__device__ float g_vtab[4 * EDIM * HH];
__device__ int   g_deg[Nn];
__device__ int   g_rowptr[Nn + 1];
__device__ int   g_cursor[Nn];
__device__ int   g_csrsrc[Ee];
__device__ int   g_csreid[Ee];
__device__ float g_bnsum[EMB];
__device__ float g_bnsq[EMB];
__device__ int   g_gs[GG];
__device__ int   g_ge[GG];

// ---------------- packed f32x2 helpers ----------------
__device__ __forceinline__ unsigned long long pk2(float x, float y) {
    unsigned long long r;
    asm("mov.b64 %0, {%1,%2};" : "=l"(r) : "f"(x), "f"(y));
    return r;
}
__device__ __forceinline__ float2 upk(unsigned long long v) {
    float2 r;
    asm("mov.b64 {%0,%1}, %2;" : "=f"(r.x), "=f"(r.y) : "l"(v));
    return r;
}
__device__ __forceinline__ void fma2(unsigned long long& d, unsigned long long a, unsigned long long b) {
    asm("fma.rn.f32x2 %0, %1, %2, %3;" : "=l"(d) : "l"(a), "l"(b), "l"(d));
}
__device__ __forceinline__ void add2(unsigned long long& d, unsigned long long a) {
    asm("add.rn.f32x2 %0, %1, %2;" : "=l"(d) : "l"(d), "l"(a));
}

// ---------------- small utility kernels ----------------
__global__ void zero_i_kernel(int* p, int n) {
    int i = blockIdx.x * blockDim.x + threadIdx.x;
    if (i < n) p[i] = 0;
}
__global__ void zero_bn_kernel() {
    int i = threadIdx.x;
    if (i < EMB) { g_bnsum[i] = 0.f; g_bnsq[i] = 0.f; }
}

// ---------------- CSR build ----------------
__global__ void deg_kernel(const int* __restrict__ dst) {
    int e = blockIdx.x * blockDim.x + threadIdx.x;
    if (e < Ee) atomicAdd(&g_deg[dst[e]], 1);
}

__global__ void scan_kernel() {
    __shared__ int sh[1024];
    __shared__ int carry;
    int t = threadIdx.x;
    if (t == 0) carry = 0;
    __syncthreads();
    for (int base = 0; base < Nn; base += 1024) {
        int v = (base + t < Nn) ? g_deg[base + t] : 0;
        sh[t] = v;
        __syncthreads();
        for (int d = 1; d < 1024; d <<= 1) {
            int x = (t >= d) ? sh[t - d] : 0;
            __syncthreads();
            sh[t] += x;
            __syncthreads();
        }
        int excl = carry + sh[t] - v;
        if (base + t < Nn) { g_rowptr[base + t] = excl; g_cursor[base + t] = excl; }
        __syncthreads();
        if (t == 0) carry += sh[1023];
        __syncthreads();
    }
    if (t == 0) g_rowptr[Nn] = carry;
}

__global__ void scatter_kernel(const int* __restrict__ src, const int* __restrict__ dst) {
    int e = blockIdx.x * blockDim.x + threadIdx.x;
    if (e >= Ee) return;
    int d = dst[e];
    int p = atomicAdd(&g_cursor[d], 1);
    g_csrsrc[p] = src[e];
    g_csreid[p] = e;
}

// ---------------- edge attention precompute ----------------
__global__ void vtab_kernel(const float* __restrict__ g0_edge, const float* __restrict__ g_edge,
                            const float* __restrict__ g0_aedge, const float* __restrict__ g_aedge) {
    int idx = blockIdx.x;                 // L*44 + d*4 + h
    int L = idx / (EDIM * HH);
    int r = idx % (EDIM * HH);
    int d = r / HH, h = r % HH;
    const float* ew = (L == 0) ? g0_edge : g_edge + (size_t)(L - 1) * EDIM * HC;
    const float* ae = (L == 0) ? g0_aedge : g_aedge + (size_t)(L - 1) * HH * CC;
    int c = threadIdx.x;                  // 128 threads
    float p = ew[d * HC + h * CC + c] * ae[h * CC + c];
    __shared__ float sw[4];
    for (int o = 16; o; o >>= 1) p += __shfl_xor_sync(0xffffffffu, p, o);
    if ((c & 31) == 0) sw[c >> 5] = p;
    __syncthreads();
    if (c == 0) g_vtab[idx] = sw[0] + sw[1] + sw[2] + sw[3];
}

__global__ void eatt_kernel(const float* __restrict__ ea) {
    __shared__ float v[4 * EDIM * HH];
    for (int i = threadIdx.x; i < 4 * EDIM * HH; i += blockDim.x) v[i] = g_vtab[i];
    __syncthreads();
    int e = blockIdx.x * blockDim.x + threadIdx.x;
    if (e >= Ee) return;
    float a[EDIM];
#pragma unroll
    for (int d = 0; d < EDIM; d++) a[d] = ea[(size_t)e * EDIM + d];
#pragma unroll
    for (int L = 0; L < 4; L++) {
#pragma unroll
        for (int h = 0; h < HH; h++) {
            float s = 0.f;
#pragma unroll
            for (int d = 0; d < EDIM; d++) s += a[d] * v[L * 44 + d * 4 + h];
            g_eatt[(size_t)e * 16 + L * 4 + h] = s;
        }
    }
}

// ---------------- GEMM: C[M,N] = A[M,K] @ B[K,N] (+bias), FFMA2 ----------------
// MODE 0: plain. MODE 1: tanh applied to A on load. MODE 2: fused per-head
// attention epilogue (requires GBN==CC and N multiple of 128).
#define GBM 128
#define GBN 128
#define GBK 16

template <int MODE>
__global__ void __launch_bounds__(256, 2) gemm128_kernel(
    const float* __restrict__ A, const float* __restrict__ B,
    const float* __restrict__ bias, float* __restrict__ C,
    int M, int N, int K,
    const float* __restrict__ att_s, const float* __restrict__ att_d)
{
    __shared__ __align__(16) unsigned long long sA2[GBK][GBM + 2];  // {v,v} duplicated
    __shared__ __align__(16) float sB[GBK][GBN];

    int tid = threadIdx.x;
    int tx = tid & 15, ty = tid >> 4;
    int rowBase = blockIdx.y * GBM, colBase = blockIdx.x * GBN;

    unsigned long long acc[8][4];
#pragma unroll
    for (int m = 0; m < 8; m++)
#pragma unroll
        for (int p = 0; p < 4; p++) acc[m][p] = 0ull;

    for (int k0 = 0; k0 < K; k0 += GBK) {
        // A tile: 128 rows x 16 k, scalar guarded loads, duplicated into u64
#pragma unroll
        for (int i = 0; i < 8; i++) {
            int idx = tid + i * 256;
            int r = idx >> 4, kk = idx & 15;
            int gr = rowBase + r, gk = k0 + kk;
            float v = (gr < M && gk < K) ? A[(size_t)gr * K + gk] : 0.f;
            if (MODE == 1) v = tanhf(v);
            sA2[kk][r] = pk2(v, v);
        }
        // B tile: 16 k x 128 cols, float4 loads
#pragma unroll
        for (int i = 0; i < 2; i++) {
            int idx = tid + i * 256;
            int kk = idx >> 5, c = (idx & 31) * 4;
            int gk = k0 + kk;
            float4 v = make_float4(0.f, 0.f, 0.f, 0.f);
            if (gk < K) v = *(const float4*)&B[(size_t)gk * N + colBase + c];
            *(float4*)&sB[kk][c] = v;
        }
        __syncthreads();
#pragma unroll
        for (int kk = 0; kk < GBK; kk++) {
            unsigned long long a8[8];
            *(ulonglong2*)&a8[0] = *(const ulonglong2*)&sA2[kk][ty * 8 + 0];
            *(ulonglong2*)&a8[2] = *(const ulonglong2*)&sA2[kk][ty * 8 + 2];
            *(ulonglong2*)&a8[4] = *(const ulonglong2*)&sA2[kk][ty * 8 + 4];
            *(ulonglong2*)&a8[6] = *(const ulonglong2*)&sA2[kk][ty * 8 + 6];
            unsigned long long b4[4];
            *(ulonglong2*)&b4[0] = *(const ulonglong2*)&sB[kk][tx * 8 + 0];
            *(ulonglong2*)&b4[2] = *(const ulonglong2*)&sB[kk][tx * 8 + 4];
#pragma unroll
            for (int m = 0; m < 8; m++)
#pragma unroll
                for (int p = 0; p < 4; p++) fma2(acc[m][p], a8[m], b4[p]);
        }
        __syncthreads();
    }

    // fused attention epilogue (xs GEMM): col tile == one head
    if (MODE == 2) {
        int head = colBase >> 7;
        float2 aw[4], dw[4];
#pragma unroll
        for (int p = 0; p < 4; p++) {
            aw[p] = upk(*(const unsigned long long*)&att_s[head * CC + tx * 8 + 2 * p]);
            dw[p] = upk(*(const unsigned long long*)&att_d[head * CC + tx * 8 + 2 * p]);
        }
#pragma unroll
        for (int m = 0; m < 8; m++) {
            float ps = 0.f, pd = 0.f;
#pragma unroll
            for (int p = 0; p < 4; p++) {
                float2 f = upk(acc[m][p]);
                ps += f.x * aw[p].x + f.y * aw[p].y;
                pd += f.x * dw[p].x + f.y * dw[p].y;
            }
#pragma unroll
            for (int o = 8; o; o >>= 1) {
                ps += __shfl_xor_sync(0xffffffffu, ps, o);
                pd += __shfl_xor_sync(0xffffffffu, pd, o);
            }
            int gr = rowBase + ty * 8 + m;
            if (tx == 0 && gr < M) {
                g_asrcn[gr * HH + head] = ps;
                g_adstn[gr * HH + head] = pd;
            }
        }
    }

    // store C (+bias)
    unsigned long long bb[4];
    if (bias) {
#pragma unroll
        for (int p = 0; p < 4; p++)
            bb[p] = *(const unsigned long long*)&bias[colBase + tx * 8 + 2 * p];
    }
#pragma unroll
    for (int m = 0; m < 8; m++) {
        int gr = rowBase + ty * 8 + m;
        if (gr >= M) continue;
        unsigned long long* crow = (unsigned long long*)&C[(size_t)gr * N + colBase + tx * 8];
#pragma unroll
        for (int p = 0; p < 4; p++) {
            unsigned long long v = acc[m][p];
            if (bias) add2(v, bb[p]);
            crow[p] = v;
        }
    }
}

// ---------------- softmax + aggregation: one warp per dst ----------------
__device__ __forceinline__ float lrelu(float a) { return a > 0.f ? a : 0.2f * a; }

__global__ void agg_kernel(int layer, const float* __restrict__ bias) {
    int gw = (blockIdx.x * blockDim.x + threadIdx.x) >> 5;
    int lane = threadIdx.x & 31;
    if (gw >= Nn) return;
    int n = gw;
    int beg = g_rowptr[n], end = g_rowptr[n + 1];
    int deg = end - beg;
    float4 ad = *(const float4*)&g_adstn[n * HH];

    // phase 1: max + edge-att sum (for self-loop mean)
    float m0 = -1e30f, m1 = -1e30f, m2 = -1e30f, m3 = -1e30f;
    float e0 = 0.f, e1 = 0.f, e2 = 0.f, e3 = 0.f;
    for (int j = beg + lane; j < end; j += 32) {
        int s = g_csrsrc[j], eid = g_csreid[j];
        float4 as = *(const float4*)&g_asrcn[s * HH];
        float4 ev = *(const float4*)&g_eatt[(size_t)eid * 16 + layer * 4];
        m0 = fmaxf(m0, lrelu(as.x + ad.x + ev.x)); e0 += ev.x;
        m1 = fmaxf(m1, lrelu(as.y + ad.y + ev.y)); e1 += ev.y;
        m2 = fmaxf(m2, lrelu(as.z + ad.z + ev.z)); e2 += ev.z;
        m3 = fmaxf(m3, lrelu(as.w + ad.w + ev.w)); e3 += ev.w;
    }
    for (int o = 16; o; o >>= 1) {
        m0 = fmaxf(m0, __shfl_xor_sync(0xffffffffu, m0, o));
        m1 = fmaxf(m1, __shfl_xor_sync(0xffffffffu, m1, o));
        m2 = fmaxf(m2, __shfl_xor_sync(0xffffffffu, m2, o));
        m3 = fmaxf(m3, __shfl_xor_sync(0xffffffffu, m3, o));
        e0 += __shfl_xor_sync(0xffffffffu, e0, o);
        e1 += __shfl_xor_sync(0xffffffffu, e1, o);
        e2 += __shfl_xor_sync(0xffffffffu, e2, o);
        e3 += __shfl_xor_sync(0xffffffffu, e3, o);
    }
    float4 asn = *(const float4*)&g_asrcn[n * HH];
    float invd = 1.f / fmaxf((float)deg, 1.f);
    float sa0 = lrelu(asn.x + ad.x + e0 * invd);
    float sa1 = lrelu(asn.y + ad.y + e1 * invd);
    float sa2 = lrelu(asn.z + ad.z + e2 * invd);
    float sa3 = lrelu(asn.w + ad.w + e3 * invd);
    m0 = fmaxf(m0, sa0); m1 = fmaxf(m1, sa1); m2 = fmaxf(m2, sa2); m3 = fmaxf(m3, sa3);

    // phase 2: denominators
    float d0 = 0.f, d1 = 0.f, d2 = 0.f, d3 = 0.f;
    for (int j = beg + lane; j < end; j += 32) {
        int s = g_csrsrc[j], eid = g_csreid[j];
        float4 as = *(const float4*)&g_asrcn[s * HH];
        float4 ev = *(const float4*)&g_eatt[(size_t)eid * 16 + layer * 4];
        d0 += expf(lrelu(as.x + ad.x + ev.x) - m0);
        d1 += expf(lrelu(as.y + ad.y + ev.y) - m1);
        d2 += expf(lrelu(as.z + ad.z + ev.z) - m2);
        d3 += expf(lrelu(as.w + ad.w + ev.w) - m3);
    }
    for (int o = 16; o; o >>= 1) {
        d0 += __shfl_xor_sync(0xffffffffu, d0, o);
        d1 += __shfl_xor_sync(0xffffffffu, d1, o);
        d2 += __shfl_xor_sync(0xffffffffu, d2, o);
        d3 += __shfl_xor_sync(0xffffffffu, d3, o);
    }
    float ws0 = expf(sa0 - m0), ws1 = expf(sa1 - m1), ws2 = expf(sa2 - m2), ws3 = expf(sa3 - m3);
    d0 += ws0; d1 += ws1; d2 += ws2; d3 += ws3;
    float id0 = 1.f / d0, id1 = 1.f / d1, id2 = 1.f / d2, id3 = 1.f / d3;
    ws0 *= id0; ws1 *= id1; ws2 *= id2; ws3 *= id3;

    // phase 3: weighted aggregation
    const float4* xr = (const float4*)&g_xs[(size_t)n * HC];
    float4 x0 = xr[lane], x1 = xr[32 + lane], x2 = xr[64 + lane], x3 = xr[96 + lane];
    float4 a0, a1, a2, a3;
    a0.x = ws0 * x0.x; a0.y = ws0 * x0.y; a0.z = ws0 * x0.z; a0.w = ws0 * x0.w;
    a1.x = ws1 * x1.x; a1.y = ws1 * x1.y; a1.z = ws1 * x1.z; a1.w = ws1 * x1.w;
    a2.x = ws2 * x2.x; a2.y = ws2 * x2.y; a2.z = ws2 * x2.z; a2.w = ws2 * x2.w;
    a3.x = ws3 * x3.x; a3.y = ws3 * x3.y; a3.z = ws3 * x3.z; a3.w = ws3 * x3.w;

    for (int j = beg; j < end; j++) {
        int s = g_csrsrc[j], eid = g_csreid[j];
        float4 as = *(const float4*)&g_asrcn[s * HH];
        float4 ev = *(const float4*)&g_eatt[(size_t)eid * 16 + layer * 4];
        float w0 = expf(lrelu(as.x + ad.x + ev.x) - m0) * id0;
        float w1 = expf(lrelu(as.y + ad.y + ev.y) - m1) * id1;
        float w2 = expf(lrelu(as.z + ad.z + ev.z) - m2) * id2;
        float w3 = expf(lrelu(as.w + ad.w + ev.w) - m3) * id3;
        const float4* sr = (const float4*)&g_xs[(size_t)s * HC];
        float4 v0 = sr[lane], v1 = sr[32 + lane], v2 = sr[64 + lane], v3 = sr[96 + lane];
        a0.x += w0 * v0.x; a0.y += w0 * v0.y; a0.z += w0 * v0.z; a0.w += w0 * v0.w;
        a1.x += w1 * v1.x; a1.y += w1 * v1.y; a1.z += w1 * v1.z; a1.w += w1 * v1.w;
        a2.x += w2 * v2.x; a2.y += w2 * v2.y; a2.z += w2 * v2.z; a2.w += w2 * v2.w;
        a3.x += w3 * v3.x; a3.y += w3 * v3.y; a3.z += w3 * v3.z; a3.w += w3 * v3.w;
    }

    const float4* b4 = (const float4*)bias;
    float4 bb;
    float4* orow = (float4*)&g_out[(size_t)n * HC];
    bb = b4[lane];       a0.x += bb.x; a0.y += bb.y; a0.z += bb.z; a0.w += bb.w; orow[lane] = a0;
    bb = b4[32 + lane];  a1.x += bb.x; a1.y += bb.y; a1.z += bb.z; a1.w += bb.w; orow[32 + lane] = a1;
    bb = b4[64 + lane];  a2.x += bb.x; a2.y += bb.y; a2.z += bb.z; a2.w += bb.w; orow[64 + lane] = a2;
    bb = b4[96 + lane];  a3.x += bb.x; a3.y += bb.y; a3.z += bb.z; a3.w += bb.w; orow[96 + lane] = a3;
}

// ---------------- batchnorm ----------------
__global__ void bn_stats_kernel() {
    int c = threadIdx.x;                 // 128
    int r0 = blockIdx.x * 128;
    int r1 = min(r0 + 128, Nn);
    float s = 0.f, q = 0.f;
    for (int r = r0; r < r1; r++) {
        float v = g_h2[(size_t)r * EMB + c];
        s += v; q += v * v;
    }
    atomicAdd(&g_bnsum[c], s);
    atomicAdd(&g_bnsq[c], q);
}

__global__ void bn_apply_kernel(const float* __restrict__ gamma, const float* __restrict__ beta) {
    int i = blockIdx.x * blockDim.x + threadIdx.x;
    if (i >= Nn * EMB) return;
    int c = i & (EMB - 1);
    float mu = g_bnsum[c] * (1.f / Nn);
    float var = g_bnsq[c] * (1.f / Nn) - mu * mu;
    g_h[i] = (g_h2[i] - mu) * rsqrtf(var + 1e-5f) * gamma[c] + beta[c];
}

// ---------------- pooling ----------------
__global__ void gb_init_kernel() {
    int g = blockIdx.x * blockDim.x + threadIdx.x;
    if (g < GG) { g_gs[g] = Nn; g_ge[g] = 0; }
}
__global__ void gb_bounds_kernel(const int* __restrict__ batch) {
    int n = blockIdx.x * blockDim.x + threadIdx.x;
    if (n >= Nn) return;
    int g = batch[n];
    atomicMin(&g_gs[g], n);
    atomicMax(&g_ge[g], n + 1);
}
__global__ void pool_kernel(float* __restrict__ d_out) {
    int g = blockIdx.x;
    int c = threadIdx.x;                 // 128
    int s = g_gs[g], e = g_ge[g];
    int cnt = (e > s) ? (e - s) : 0;
    float mx = -1e30f, sum = 0.f;
    for (int n = s; n < e; n++) {
        float v = g_h[(size_t)n * EMB + c];
        mx = fmaxf(mx, v);
        sum += v;
    }
    float* hid = d_out + GG + (size_t)g * 2 * EMB;
    hid[c] = (cnt > 0) ? mx : 0.f;
    hid[EMB + c] = (cnt > 0) ? sum / (float)cnt : 0.f;
}

// ---------------- readout MLP ----------------
__global__ void mlp_kernel(const float* __restrict__ w1, const float* __restrict__ b1,
                           const float* __restrict__ w2, const float* __restrict__ b2,
                           float* __restrict__ d_out) {
    __shared__ float hid[256];
    __shared__ float o[256];
    int g = blockIdx.x;
    int t = threadIdx.x;                 // 256
    hid[t] = d_out[GG + (size_t)g * 256 + t];
    __syncthreads();
    float s = b1[t];
#pragma unroll 8
    for (int k = 0; k < 256; k++) s += hid[k] * w1[(size_t)k * 256 + t];
    s = s > 0.f ? s : 0.f;
    o[t] = s * w2[t];
    __syncthreads();
    for (int d = 128; d; d >>= 1) {
        if (t < d) o[t] += o[t + d];
        __syncthreads();
    }
    if (t == 0) d_out[g] = o[0] + b2[0];
}

// ---------------- driver ----------------
extern "C" void kernel_launch(void* const* d_in, const int* in_sizes, int n_in,
                              void* d_out_v, int out_size) {
    const float* x         = (const float*)d_in[0];
    const int*   edge_idx  = (const int*)d_in[1];
    const float* edge_attr = (const float*)d_in[2];
    const int*   batch     = (const int*)d_in[3];
    const float* g0_lin    = (const float*)d_in[4];
    const float* g0_edge   = (const float*)d_in[5];
    const float* g0_asrc   = (const float*)d_in[6];
    const float* g0_adst   = (const float*)d_in[7];
    const float* g0_aedge  = (const float*)d_in[8];
    const float* g0_b      = (const float*)d_in[9];
    const float* g_lin     = (const float*)d_in[10];
    const float* g_edge    = (const float*)d_in[11];
    const float* g_asrc    = (const float*)d_in[12];
    const float* g_adst    = (const float*)d_in[13];
    const float* g_aedge   = (const float*)d_in[14];
    const float* g_b       = (const float*)d_in[15];
    const float* ht_w      = (const float*)d_in[16];
    const float* ht_b      = (const float*)d_in[17];
    const float* bn_g      = (const float*)d_in[18];
    const float* bn_b      = (const float*)d_in[19];
    const float* out1_w    = (const float*)d_in[20];
    const float* out1_b    = (const float*)d_in[21];
    const float* out2_w    = (const float*)d_in[22];
    const float* out2_b    = (const float*)d_in[23];
    float* d_out = (float*)d_out_v;

    const int* src = edge_idx;
    const int* dst = edge_idx + Ee;

    // CSR build
    int* degPtr = nullptr;
    cudaGetSymbolAddress((void**)&degPtr, g_deg);
    zero_i_kernel<<<(Nn + 255) / 256, 256>>>(degPtr, Nn);
    deg_kernel<<<(Ee + 255) / 256, 256>>>(dst);
    scan_kernel<<<1, 1024>>>();
    scatter_kernel<<<(Ee + 255) / 256, 256>>>(src, dst);

    // edge attention precompute for all 4 layers
    vtab_kernel<<<4 * EDIM * HH, 128>>>(g0_edge, g_edge, g0_aedge, g_aedge);
    eatt_kernel<<<(Ee + 127) / 128, 128>>>(edge_attr);

    float* xsPtr = nullptr;  cudaGetSymbolAddress((void**)&xsPtr, g_xs);
    float* outPtr = nullptr; cudaGetSymbolAddress((void**)&outPtr, g_out);
    float* hPtr = nullptr;   cudaGetSymbolAddress((void**)&hPtr, g_h);
    float* h2Ptr = nullptr;  cudaGetSymbolAddress((void**)&h2Ptr, g_h2);

    const int tilesM = (Nn + GBM - 1) / GBM;   // 157

    for (int L = 0; L < 4; L++) {
        const float* lin  = (L == 0) ? g0_lin  : g_lin  + (size_t)(L - 1) * EMB * HC;
        const float* as_  = (L == 0) ? g0_asrc : g_asrc + (size_t)(L - 1) * HH * CC;
        const float* ad_  = (L == 0) ? g0_adst : g_adst + (size_t)(L - 1) * HH * CC;
        const float* bia  = (L == 0) ? g0_b    : g_b    + (size_t)(L - 1) * HC;
        const float* hin  = (L == 0) ? x : hPtr;
        int K = (L == 0) ? FIN : EMB;

        // xs = h_in @ lin  [N, HC], with fused per-head attention logits
        gemm128_kernel<2><<<dim3(HC / GBN, tilesM), 256>>>(
            hin, lin, nullptr, xsPtr, Nn, HC, K, as_, ad_);
        // softmax + aggregation (+bias)
        agg_kernel<<<(Nn * 32 + 255) / 256, 256>>>(L, bia);
        // head transform with fused tanh on A: h2 = tanh(out) @ ht_w[L] + ht_b[L]
        gemm128_kernel<1><<<dim3(EMB / GBN, tilesM), 256>>>(
            outPtr, ht_w + (size_t)L * HC * EMB, ht_b + (size_t)L * EMB,
            h2Ptr, Nn, EMB, HC, nullptr, nullptr);
        // batchnorm -> g_h
        zero_bn_kernel<<<1, 128>>>();
        bn_stats_kernel<<<(Nn + 127) / 128, 128>>>();
        bn_apply_kernel<<<(Nn * EMB + 255) / 256, 256>>>(bn_g + (size_t)L * EMB, bn_b + (size_t)L * EMB);
    }

    // pooling + readout
    gb_init_kernel<<<(GG + 255) / 256, 256>>>();
    gb_bounds_kernel<<<(Nn + 255) / 256, 256>>>(batch);
    pool_kernel<<<GG, 128>>>(d_out);
    mlp_kernel<<<GG, 256>>>(out1_w, out1_b, out2_w, out2_b, d_out);
}

// round 5
// speedup vs baseline: 1.8403x; 1.3030x over previous
#include <cuda_runtime.h>
#include <math.h>

#define Nn 20000
#define Ee 160000
#define FIN 30
#define EDIM 11
#define HH 4
#define CC 128
#define HC 512
#define EMB 128
#define GG 1000
#define NBLK 20   /* ceil(Nn/1024) */

// ---------------- scratch (device globals; no allocation) ----------------
__device__ float g_xs[Nn * HC];
__device__ float g_out[Nn * HC];
__device__ float g_h[Nn * EMB];
__device__ float g_h2[Nn * EMB];
__device__ float g_asrcn[Nn * HH];
__device__ float g_adstn[Nn * HH];
__device__ float g_eatt[Ee * 16];
__device__ float g_vtab[4 * EDIM * HH];
__device__ int   g_deg[Nn];
__device__ int   g_rowptr[Nn + 1];
__device__ int   g_cursor[Nn];
__device__ int   g_csrsrc[Ee];
__device__ int   g_csreid[Ee];
__device__ float g_bnsum[EMB];
__device__ float g_bnsq[EMB];
__device__ int   g_gs[GG];
__device__ int   g_ge[GG];
__device__ int   g_blksum[NBLK];
__device__ int   g_blkoff[NBLK];

// ---------------- packed f32x2 helpers ----------------
__device__ __forceinline__ unsigned long long pk2(float x, float y) {
    unsigned long long r;
    asm("mov.b64 %0, {%1,%2};" : "=l"(r) : "f"(x), "f"(y));
    return r;
}
__device__ __forceinline__ float2 upk(unsigned long long v) {
    float2 r;
    asm("mov.b64 {%0,%1}, %2;" : "=f"(r.x), "=f"(r.y) : "l"(v));
    return r;
}
__device__ __forceinline__ void fma2(unsigned long long& d, unsigned long long a, unsigned long long b) {
    asm("fma.rn.f32x2 %0, %1, %2, %3;" : "=l"(d) : "l"(a), "l"(b), "l"(d));
}

// ---------------- small utility kernels ----------------
__global__ void zero_i_kernel(int* p, int n) {
    int i = blockIdx.x * blockDim.x + threadIdx.x;
    if (i < n) p[i] = 0;
}
__global__ void zero_bn_kernel() {
    int i = threadIdx.x;
    if (i < EMB) { g_bnsum[i] = 0.f; g_bnsq[i] = 0.f; }
}

// ---------------- CSR build ----------------
__global__ void deg_kernel(const int* __restrict__ dst) {
    int e = blockIdx.x * blockDim.x + threadIdx.x;
    if (e < Ee) atomicAdd(&g_deg[dst[e]], 1);
}

// hierarchical scan: per-block inclusive scan + block sums
__global__ void scan1_kernel() {
    __shared__ int sh[1024];
    int b = blockIdx.x, t = threadIdx.x;
    int i = b * 1024 + t;
    int v = (i < Nn) ? g_deg[i] : 0;
    sh[t] = v;
    __syncthreads();
    for (int d = 1; d < 1024; d <<= 1) {
        int x = (t >= d) ? sh[t - d] : 0;
        __syncthreads();
        sh[t] += x;
        __syncthreads();
    }
    if (i < Nn) g_rowptr[i] = sh[t] - v;   // exclusive within block
    if (t == 1023) g_blksum[b] = sh[1023];
}
__global__ void scan2_kernel() {
    if (threadIdx.x == 0) {
        int s = 0;
        for (int b = 0; b < NBLK; b++) { g_blkoff[b] = s; s += g_blksum[b]; }
        g_rowptr[Nn] = s;
    }
}
__global__ void scan3_kernel() {
    int i = blockIdx.x * blockDim.x + threadIdx.x;
    if (i < Nn) {
        int v = g_rowptr[i] + g_blkoff[i >> 10];
        g_rowptr[i] = v;
        g_cursor[i] = v;
    }
}

__global__ void scatter_kernel(const int* __restrict__ src, const int* __restrict__ dst) {
    int e = blockIdx.x * blockDim.x + threadIdx.x;
    if (e >= Ee) return;
    int d = dst[e];
    int p = atomicAdd(&g_cursor[d], 1);
    g_csrsrc[p] = src[e];
    g_csreid[p] = e;
}

// ---------------- edge attention precompute ----------------
__global__ void vtab_kernel(const float* __restrict__ g0_edge, const float* __restrict__ g_edge,
                            const float* __restrict__ g0_aedge, const float* __restrict__ g_aedge) {
    int idx = blockIdx.x;                 // L*44 + d*4 + h
    int L = idx / (EDIM * HH);
    int r = idx % (EDIM * HH);
    int d = r / HH, h = r % HH;
    const float* ew = (L == 0) ? g0_edge : g_edge + (size_t)(L - 1) * EDIM * HC;
    const float* ae = (L == 0) ? g0_aedge : g_aedge + (size_t)(L - 1) * HH * CC;
    int c = threadIdx.x;                  // 128 threads
    float p = ew[d * HC + h * CC + c] * ae[h * CC + c];
    __shared__ float sw[4];
    for (int o = 16; o; o >>= 1) p += __shfl_xor_sync(0xffffffffu, p, o);
    if ((c & 31) == 0) sw[c >> 5] = p;
    __syncthreads();
    if (c == 0) g_vtab[idx] = sw[0] + sw[1] + sw[2] + sw[3];
}

__global__ void eatt_kernel(const float* __restrict__ ea) {
    __shared__ float v[4 * EDIM * HH];
    for (int i = threadIdx.x; i < 4 * EDIM * HH; i += blockDim.x) v[i] = g_vtab[i];
    __syncthreads();
    int e = blockIdx.x * blockDim.x + threadIdx.x;
    if (e >= Ee) return;
    float a[EDIM];
#pragma unroll
    for (int d = 0; d < EDIM; d++) a[d] = ea[(size_t)e * EDIM + d];
#pragma unroll
    for (int L = 0; L < 4; L++) {
#pragma unroll
        for (int h = 0; h < HH; h++) {
            float s = 0.f;
#pragma unroll
            for (int d = 0; d < EDIM; d++) s += a[d] * v[L * 44 + d * 4 + h];
            g_eatt[(size_t)e * 16 + L * 4 + h] = s;
        }
    }
}

// ---------------- GEMM: C[M,N] = A[M,K] @ B[K,N] (+bias), FFMA2 ----------------
// MODE bits: 1 = tanh(A) on load, 2 = fused attention epilogue (GBN==CC),
//            4 = batchnorm-normalize A on load (K == EMB).
#define GBM 128
#define GBN 128
#define GBK 16

template <int MODE>
__global__ void __launch_bounds__(256, 2) gemm128_kernel(
    const float* __restrict__ A, const float* __restrict__ B,
    const float* __restrict__ bias, float* __restrict__ C,
    int M, int N, int K,
    const float* __restrict__ att_s, const float* __restrict__ att_d,
    const float* __restrict__ bnG, const float* __restrict__ bnB)
{
    __shared__ __align__(16) float sA[GBK][GBM + 4];   // [k][row]
    __shared__ __align__(16) float sB[GBK][GBN];

    int tid = threadIdx.x;
    int tx = tid & 15, ty = tid >> 4;
    int rowBase = blockIdx.y * GBM, colBase = blockIdx.x * GBN;
    const bool vecA = ((K & 3) == 0);     // float4 A path legal only if rows stay 16B-aligned

    unsigned long long acc[4][8];   // [M-pair][n]
#pragma unroll
    for (int p = 0; p < 4; p++)
#pragma unroll
        for (int n = 0; n < 8; n++) acc[p][n] = 0ull;

    float4 aR[2], bR[2];
    int T = (K + GBK - 1) / GBK;

    // ---- tile loaders (to registers) ----
    auto loadT = [&](int k0) {
#pragma unroll
        for (int pp = 0; pp < 2; pp++) {
            int idx = tid + pp * 256;              // 0..511
            int r = idx >> 2, kq = (idx & 3) * 4;  // r:0..127, kq:{0,4,8,12}
            int gr = rowBase + r, gk = k0 + kq;
            float4 v = make_float4(0.f, 0.f, 0.f, 0.f);
            if (gr < M) {
                if (vecA && gk + 3 < K) {
                    v = *(const float4*)&A[(size_t)gr * K + gk];
                } else {
                    float* pv = &v.x;
#pragma unroll
                    for (int j = 0; j < 4; j++)
                        if (gk + j < K) pv[j] = A[(size_t)gr * K + gk + j];
                }
            }
            if (MODE & 1) {
                v.x = tanhf(v.x); v.y = tanhf(v.y); v.z = tanhf(v.z); v.w = tanhf(v.w);
            }
            if (MODE & 4) {
                float* pv = &v.x;
#pragma unroll
                for (int j = 0; j < 4; j++) {
                    int ch = gk + j;               // K == EMB
                    float mu = g_bnsum[ch] * (1.f / Nn);
                    float var = g_bnsq[ch] * (1.f / Nn) - mu * mu;
                    pv[j] = (pv[j] - mu) * rsqrtf(var + 1e-5f) * bnG[ch] + bnB[ch];
                }
            }
            aR[pp] = v;
        }
#pragma unroll
        for (int pp = 0; pp < 2; pp++) {
            int idx = tid + pp * 256;
            int kk = idx >> 5, c4 = (idx & 31) * 4;
            int gk = k0 + kk;
            float4 v = make_float4(0.f, 0.f, 0.f, 0.f);
            if (gk < K) v = *(const float4*)&B[(size_t)gk * N + colBase + c4];
            bR[pp] = v;
        }
    };
    auto storeT = [&]() {
#pragma unroll
        for (int pp = 0; pp < 2; pp++) {
            int idx = tid + pp * 256;
            int r = idx >> 2, kq = (idx & 3) * 4;
            sA[kq + 0][r] = aR[pp].x;
            sA[kq + 1][r] = aR[pp].y;
            sA[kq + 2][r] = aR[pp].z;
            sA[kq + 3][r] = aR[pp].w;
        }
#pragma unroll
        for (int pp = 0; pp < 2; pp++) {
            int idx = tid + pp * 256;
            int kk = idx >> 5, c4 = (idx & 31) * 4;
            *(float4*)&sB[kk][c4] = bR[pp];
        }
    };

    loadT(0);
    for (int t = 0; t < T; t++) {
        storeT();
        __syncthreads();
        if (t + 1 < T) loadT((t + 1) * GBK);
#pragma unroll
        for (int kk = 0; kk < GBK; kk++) {
            ulonglong2 q0 = *(const ulonglong2*)&sA[kk][ty * 8];
            ulonglong2 q1 = *(const ulonglong2*)&sA[kk][ty * 8 + 4];
            unsigned long long aP[4] = {q0.x, q0.y, q1.x, q1.y};
            float4 bv0 = *(const float4*)&sB[kk][tx * 4];
            float4 bv1 = *(const float4*)&sB[kk][64 + tx * 4];
            unsigned long long bD[8];
            bD[0] = pk2(bv0.x, bv0.x); bD[1] = pk2(bv0.y, bv0.y);
            bD[2] = pk2(bv0.z, bv0.z); bD[3] = pk2(bv0.w, bv0.w);
            bD[4] = pk2(bv1.x, bv1.x); bD[5] = pk2(bv1.y, bv1.y);
            bD[6] = pk2(bv1.z, bv1.z); bD[7] = pk2(bv1.w, bv1.w);
#pragma unroll
            for (int p = 0; p < 4; p++)
#pragma unroll
                for (int n = 0; n < 8; n++) fma2(acc[p][n], aP[p], bD[n]);
        }
        __syncthreads();
    }

    // fused attention epilogue: col tile == one head
    if (MODE & 2) {
        int head = colBase >> 7;
        float aw[8], dw[8];
#pragma unroll
        for (int n = 0; n < 4; n++) {
            aw[n] = att_s[head * CC + tx * 4 + n];
            dw[n] = att_d[head * CC + tx * 4 + n];
            aw[n + 4] = att_s[head * CC + 64 + tx * 4 + n];
            dw[n + 4] = att_d[head * CC + 64 + tx * 4 + n];
        }
#pragma unroll
        for (int p = 0; p < 4; p++) {
            float psx = 0.f, psy = 0.f, pdx = 0.f, pdy = 0.f;
#pragma unroll
            for (int n = 0; n < 8; n++) {
                float2 f = upk(acc[p][n]);
                psx += f.x * aw[n]; psy += f.y * aw[n];
                pdx += f.x * dw[n]; pdy += f.y * dw[n];
            }
#pragma unroll
            for (int o = 8; o; o >>= 1) {
                psx += __shfl_xor_sync(0xffffffffu, psx, o);
                psy += __shfl_xor_sync(0xffffffffu, psy, o);
                pdx += __shfl_xor_sync(0xffffffffu, pdx, o);
                pdy += __shfl_xor_sync(0xffffffffu, pdy, o);
            }
            int r0 = rowBase + ty * 8 + 2 * p;
            if (tx == 0) {
                if (r0 < M)     { g_asrcn[r0 * HH + head] = psx;       g_adstn[r0 * HH + head] = pdx; }
                if (r0 + 1 < M) { g_asrcn[(r0 + 1) * HH + head] = psy; g_adstn[(r0 + 1) * HH + head] = pdy; }
            }
        }
    }

    // store C (+bias)
    float4 b0 = make_float4(0.f, 0.f, 0.f, 0.f), b1 = b0;
    if (bias) {
        b0 = *(const float4*)&bias[colBase + tx * 4];
        b1 = *(const float4*)&bias[colBase + 64 + tx * 4];
    }
#pragma unroll
    for (int p = 0; p < 4; p++) {
        float2 f[8];
#pragma unroll
        for (int n = 0; n < 8; n++) f[n] = upk(acc[p][n]);
        int r0 = rowBase + ty * 8 + 2 * p;
#pragma unroll
        for (int h = 0; h < 2; h++) {
            int row = r0 + h;
            if (row >= M) continue;
            float4 o0, o1;
            o0.x = (h ? f[0].y : f[0].x) + b0.x;
            o0.y = (h ? f[1].y : f[1].x) + b0.y;
            o0.z = (h ? f[2].y : f[2].x) + b0.z;
            o0.w = (h ? f[3].y : f[3].x) + b0.w;
            o1.x = (h ? f[4].y : f[4].x) + b1.x;
            o1.y = (h ? f[5].y : f[5].x) + b1.y;
            o1.z = (h ? f[6].y : f[6].x) + b1.z;
            o1.w = (h ? f[7].y : f[7].x) + b1.w;
            *(float4*)&C[(size_t)row * N + colBase + tx * 4] = o0;
            *(float4*)&C[(size_t)row * N + colBase + 64 + tx * 4] = o1;
        }
    }
}

// ---------------- softmax + aggregation: one warp per dst ----------------
__device__ __forceinline__ float lrelu(float a) { return a > 0.f ? a : 0.2f * a; }

__global__ void agg_kernel(int layer, const float* __restrict__ bias) {
    int gw = (blockIdx.x * blockDim.x + threadIdx.x) >> 5;
    int lane = threadIdx.x & 31;
    if (gw >= Nn) return;
    int n = gw;
    int beg = g_rowptr[n], end = g_rowptr[n + 1];
    int deg = end - beg;
    float4 ad = *(const float4*)&g_adstn[n * HH];

    // phase 1: max + edge-att sum (for self-loop mean)
    float m0 = -1e30f, m1 = -1e30f, m2 = -1e30f, m3 = -1e30f;
    float e0 = 0.f, e1 = 0.f, e2 = 0.f, e3 = 0.f;
    for (int j = beg + lane; j < end; j += 32) {
        int s = g_csrsrc[j], eid = g_csreid[j];
        float4 as = *(const float4*)&g_asrcn[s * HH];
        float4 ev = *(const float4*)&g_eatt[(size_t)eid * 16 + layer * 4];
        m0 = fmaxf(m0, lrelu(as.x + ad.x + ev.x)); e0 += ev.x;
        m1 = fmaxf(m1, lrelu(as.y + ad.y + ev.y)); e1 += ev.y;
        m2 = fmaxf(m2, lrelu(as.z + ad.z + ev.z)); e2 += ev.z;
        m3 = fmaxf(m3, lrelu(as.w + ad.w + ev.w)); e3 += ev.w;
    }
    for (int o = 16; o; o >>= 1) {
        m0 = fmaxf(m0, __shfl_xor_sync(0xffffffffu, m0, o));
        m1 = fmaxf(m1, __shfl_xor_sync(0xffffffffu, m1, o));
        m2 = fmaxf(m2, __shfl_xor_sync(0xffffffffu, m2, o));
        m3 = fmaxf(m3, __shfl_xor_sync(0xffffffffu, m3, o));
        e0 += __shfl_xor_sync(0xffffffffu, e0, o);
        e1 += __shfl_xor_sync(0xffffffffu, e1, o);
        e2 += __shfl_xor_sync(0xffffffffu, e2, o);
        e3 += __shfl_xor_sync(0xffffffffu, e3, o);
    }
    float4 asn = *(const float4*)&g_asrcn[n * HH];
    float invd = 1.f / fmaxf((float)deg, 1.f);
    float sa0 = lrelu(asn.x + ad.x + e0 * invd);
    float sa1 = lrelu(asn.y + ad.y + e1 * invd);
    float sa2 = lrelu(asn.z + ad.z + e2 * invd);
    float sa3 = lrelu(asn.w + ad.w + e3 * invd);
    m0 = fmaxf(m0, sa0); m1 = fmaxf(m1, sa1); m2 = fmaxf(m2, sa2); m3 = fmaxf(m3, sa3);

    // phase 2: denominators
    float d0 = 0.f, d1 = 0.f, d2 = 0.f, d3 = 0.f;
    for (int j = beg + lane; j < end; j += 32) {
        int s = g_csrsrc[j], eid = g_csreid[j];
        float4 as = *(const float4*)&g_asrcn[s * HH];
        float4 ev = *(const float4*)&g_eatt[(size_t)eid * 16 + layer * 4];
        d0 += expf(lrelu(as.x + ad.x + ev.x) - m0);
        d1 += expf(lrelu(as.y + ad.y + ev.y) - m1);
        d2 += expf(lrelu(as.z + ad.z + ev.z) - m2);
        d3 += expf(lrelu(as.w + ad.w + ev.w) - m3);
    }
    for (int o = 16; o; o >>= 1) {
        d0 += __shfl_xor_sync(0xffffffffu, d0, o);
        d1 += __shfl_xor_sync(0xffffffffu, d1, o);
        d2 += __shfl_xor_sync(0xffffffffu, d2, o);
        d3 += __shfl_xor_sync(0xffffffffu, d3, o);
    }
    float ws0 = expf(sa0 - m0), ws1 = expf(sa1 - m1), ws2 = expf(sa2 - m2), ws3 = expf(sa3 - m3);
    d0 += ws0; d1 += ws1; d2 += ws2; d3 += ws3;
    float id0 = 1.f / d0, id1 = 1.f / d1, id2 = 1.f / d2, id3 = 1.f / d3;
    ws0 *= id0; ws1 *= id1; ws2 *= id2; ws3 *= id3;

    // phase 3: weighted aggregation; weights computed lane-strided + shfl broadcast
    const float4* xr = (const float4*)&g_xs[(size_t)n * HC];
    float4 x0 = xr[lane], x1 = xr[32 + lane], x2 = xr[64 + lane], x3 = xr[96 + lane];
    float4 a0, a1, a2, a3;
    a0.x = ws0 * x0.x; a0.y = ws0 * x0.y; a0.z = ws0 * x0.z; a0.w = ws0 * x0.w;
    a1.x = ws1 * x1.x; a1.y = ws1 * x1.y; a1.z = ws1 * x1.z; a1.w = ws1 * x1.w;
    a2.x = ws2 * x2.x; a2.y = ws2 * x2.y; a2.z = ws2 * x2.z; a2.w = ws2 * x2.w;
    a3.x = ws3 * x3.x; a3.y = ws3 * x3.y; a3.z = ws3 * x3.z; a3.w = ws3 * x3.w;

    for (int j0 = beg; j0 < end; j0 += 32) {
        int cnt = min(32, end - j0);
        float w0 = 0.f, w1 = 0.f, w2 = 0.f, w3 = 0.f;
        int sv = 0;
        if (lane < cnt) {
            int j = j0 + lane;
            int s = g_csrsrc[j], eid = g_csreid[j];
            float4 as = *(const float4*)&g_asrcn[s * HH];
            float4 ev = *(const float4*)&g_eatt[(size_t)eid * 16 + layer * 4];
            w0 = expf(lrelu(as.x + ad.x + ev.x) - m0) * id0;
            w1 = expf(lrelu(as.y + ad.y + ev.y) - m1) * id1;
            w2 = expf(lrelu(as.z + ad.z + ev.z) - m2) * id2;
            w3 = expf(lrelu(as.w + ad.w + ev.w) - m3) * id3;
            sv = s;
        }
        for (int k = 0; k < cnt; k++) {
            float u0 = __shfl_sync(0xffffffffu, w0, k);
            float u1 = __shfl_sync(0xffffffffu, w1, k);
            float u2 = __shfl_sync(0xffffffffu, w2, k);
            float u3 = __shfl_sync(0xffffffffu, w3, k);
            int s = __shfl_sync(0xffffffffu, sv, k);
            const float4* sr = (const float4*)&g_xs[(size_t)s * HC];
            float4 v0 = sr[lane], v1 = sr[32 + lane], v2 = sr[64 + lane], v3 = sr[96 + lane];
            a0.x += u0 * v0.x; a0.y += u0 * v0.y; a0.z += u0 * v0.z; a0.w += u0 * v0.w;
            a1.x += u1 * v1.x; a1.y += u1 * v1.y; a1.z += u1 * v1.z; a1.w += u1 * v1.w;
            a2.x += u2 * v2.x; a2.y += u2 * v2.y; a2.z += u2 * v2.z; a2.w += u2 * v2.w;
            a3.x += u3 * v3.x; a3.y += u3 * v3.y; a3.z += u3 * v3.z; a3.w += u3 * v3.w;
        }
    }

    const float4* b4 = (const float4*)bias;
    float4 bb;
    float4* orow = (float4*)&g_out[(size_t)n * HC];
    bb = b4[lane];       a0.x += bb.x; a0.y += bb.y; a0.z += bb.z; a0.w += bb.w; orow[lane] = a0;
    bb = b4[32 + lane];  a1.x += bb.x; a1.y += bb.y; a1.z += bb.z; a1.w += bb.w; orow[32 + lane] = a1;
    bb = b4[64 + lane];  a2.x += bb.x; a2.y += bb.y; a2.z += bb.z; a2.w += bb.w; orow[64 + lane] = a2;
    bb = b4[96 + lane];  a3.x += bb.x; a3.y += bb.y; a3.z += bb.z; a3.w += bb.w; orow[96 + lane] = a3;
}

// ---------------- batchnorm ----------------
__global__ void bn_stats_kernel() {
    int c = threadIdx.x;                 // 128
    int r0 = blockIdx.x * 128;
    int r1 = min(r0 + 128, Nn);
    float s = 0.f, q = 0.f;
    for (int r = r0; r < r1; r++) {
        float v = g_h2[(size_t)r * EMB + c];
        s += v; q += v * v;
    }
    atomicAdd(&g_bnsum[c], s);
    atomicAdd(&g_bnsq[c], q);
}

__global__ void bn_apply_kernel(const float* __restrict__ gamma, const float* __restrict__ beta) {
    int i = blockIdx.x * blockDim.x + threadIdx.x;
    if (i >= Nn * EMB) return;
    int c = i & (EMB - 1);
    float mu = g_bnsum[c] * (1.f / Nn);
    float var = g_bnsq[c] * (1.f / Nn) - mu * mu;
    g_h[i] = (g_h2[i] - mu) * rsqrtf(var + 1e-5f) * gamma[c] + beta[c];
}

// ---------------- pooling ----------------
__global__ void gb_init_kernel() {
    int g = blockIdx.x * blockDim.x + threadIdx.x;
    if (g < GG) { g_gs[g] = Nn; g_ge[g] = 0; }
}
__global__ void gb_bounds_kernel(const int* __restrict__ batch) {
    int n = blockIdx.x * blockDim.x + threadIdx.x;
    if (n >= Nn) return;
    int g = batch[n];
    atomicMin(&g_gs[g], n);
    atomicMax(&g_ge[g], n + 1);
}
__global__ void pool_kernel(float* __restrict__ d_out) {
    int g = blockIdx.x;
    int c = threadIdx.x;                 // 128
    int s = g_gs[g], e = g_ge[g];
    int cnt = (e > s) ? (e - s) : 0;
    float mx = -1e30f, sum = 0.f;
    for (int n = s; n < e; n++) {
        float v = g_h[(size_t)n * EMB + c];
        mx = fmaxf(mx, v);
        sum += v;
    }
    float* hid = d_out + GG + (size_t)g * 2 * EMB;
    hid[c] = (cnt > 0) ? mx : 0.f;
    hid[EMB + c] = (cnt > 0) ? sum / (float)cnt : 0.f;
}

// ---------------- readout MLP ----------------
__global__ void mlp_kernel(const float* __restrict__ w1, const float* __restrict__ b1,
                           const float* __restrict__ w2, const float* __restrict__ b2,
                           float* __restrict__ d_out) {
    __shared__ float hid[256];
    __shared__ float o[256];
    int g = blockIdx.x;
    int t = threadIdx.x;                 // 256
    hid[t] = d_out[GG + (size_t)g * 256 + t];
    __syncthreads();
    float s = b1[t];
#pragma unroll 8
    for (int k = 0; k < 256; k++) s += hid[k] * w1[(size_t)k * 256 + t];
    s = s > 0.f ? s : 0.f;
    o[t] = s * w2[t];
    __syncthreads();
    for (int d = 128; d; d >>= 1) {
        if (t < d) o[t] += o[t + d];
        __syncthreads();
    }
    if (t == 0) d_out[g] = o[0] + b2[0];
}

// ---------------- driver ----------------
extern "C" void kernel_launch(void* const* d_in, const int* in_sizes, int n_in,
                              void* d_out_v, int out_size) {
    const float* x         = (const float*)d_in[0];
    const int*   edge_idx  = (const int*)d_in[1];
    const float* edge_attr = (const float*)d_in[2];
    const int*   batch     = (const int*)d_in[3];
    const float* g0_lin    = (const float*)d_in[4];
    const float* g0_edge   = (const float*)d_in[5];
    const float* g0_asrc   = (const float*)d_in[6];
    const float* g0_adst   = (const float*)d_in[7];
    const float* g0_aedge  = (const float*)d_in[8];
    const float* g0_b      = (const float*)d_in[9];
    const float* g_lin     = (const float*)d_in[10];
    const float* g_edge    = (const float*)d_in[11];
    const float* g_asrc    = (const float*)d_in[12];
    const float* g_adst    = (const float*)d_in[13];
    const float* g_aedge   = (const float*)d_in[14];
    const float* g_b       = (const float*)d_in[15];
    const float* ht_w      = (const float*)d_in[16];
    const float* ht_b      = (const float*)d_in[17];
    const float* bn_g      = (const float*)d_in[18];
    const float* bn_b      = (const float*)d_in[19];
    const float* out1_w    = (const float*)d_in[20];
    const float* out1_b    = (const float*)d_in[21];
    const float* out2_w    = (const float*)d_in[22];
    const float* out2_b    = (const float*)d_in[23];
    float* d_out = (float*)d_out_v;

    const int* src = edge_idx;
    const int* dst = edge_idx + Ee;

    // CSR build
    int* degPtr = nullptr;
    cudaGetSymbolAddress((void**)&degPtr, g_deg);
    zero_i_kernel<<<(Nn + 255) / 256, 256>>>(degPtr, Nn);
    deg_kernel<<<(Ee + 255) / 256, 256>>>(dst);
    scan1_kernel<<<NBLK, 1024>>>();
    scan2_kernel<<<1, 32>>>();
    scan3_kernel<<<(Nn + 255) / 256, 256>>>();
    scatter_kernel<<<(Ee + 255) / 256, 256>>>(src, dst);

    // edge attention precompute for all 4 layers
    vtab_kernel<<<4 * EDIM * HH, 128>>>(g0_edge, g_edge, g0_aedge, g_aedge);
    eatt_kernel<<<(Ee + 127) / 128, 128>>>(edge_attr);

    float* xsPtr = nullptr;  cudaGetSymbolAddress((void**)&xsPtr, g_xs);
    float* outPtr = nullptr; cudaGetSymbolAddress((void**)&outPtr, g_out);
    float* hPtr = nullptr;   cudaGetSymbolAddress((void**)&hPtr, g_h);
    float* h2Ptr = nullptr;  cudaGetSymbolAddress((void**)&h2Ptr, g_h2);

    const int tilesM = (Nn + GBM - 1) / GBM;   // 157

    for (int L = 0; L < 4; L++) {
        const float* lin  = (L == 0) ? g0_lin  : g_lin  + (size_t)(L - 1) * EMB * HC;
        const float* as_  = (L == 0) ? g0_asrc : g_asrc + (size_t)(L - 1) * HH * CC;
        const float* ad_  = (L == 0) ? g0_adst : g_adst + (size_t)(L - 1) * HH * CC;
        const float* bia  = (L == 0) ? g0_b    : g_b    + (size_t)(L - 1) * HC;
        int K = (L == 0) ? FIN : EMB;

        // xs = norm(h_in) @ lin  [N, HC], fused per-head attention logits.
        if (L == 0) {
            gemm128_kernel<2><<<dim3(HC / GBN, tilesM), 256>>>(
                x, lin, nullptr, xsPtr, Nn, HC, K, as_, ad_, nullptr, nullptr);
        } else {
            gemm128_kernel<6><<<dim3(HC / GBN, tilesM), 256>>>(
                h2Ptr, lin, nullptr, xsPtr, Nn, HC, K, as_, ad_,
                bn_g + (size_t)(L - 1) * EMB, bn_b + (size_t)(L - 1) * EMB);
        }
        // softmax + aggregation (+bias)
        agg_kernel<<<(Nn * 32 + 255) / 256, 256>>>(L, bia);
        // head transform with fused tanh on A: h2 = tanh(out) @ ht_w[L] + ht_b[L]
        gemm128_kernel<1><<<dim3(EMB / GBN, tilesM), 256>>>(
            outPtr, ht_w + (size_t)L * HC * EMB, ht_b + (size_t)L * EMB,
            h2Ptr, Nn, EMB, HC, nullptr, nullptr, nullptr, nullptr);
        // batchnorm stats (apply is fused into next layer's GEMM, except last)
        zero_bn_kernel<<<1, 128>>>();
        bn_stats_kernel<<<(Nn + 127) / 128, 128>>>();
    }
    // final layer BN apply -> g_h (feeds pooling)
    bn_apply_kernel<<<(Nn * EMB + 255) / 256, 256>>>(bn_g + 3 * EMB, bn_b + 3 * EMB);

    // pooling + readout
    gb_init_kernel<<<(GG + 255) / 256, 256>>>();
    gb_bounds_kernel<<<(Nn + 255) / 256, 256>>>(batch);
    pool_kernel<<<GG, 128>>>(d_out);
    mlp_kernel<<<GG, 256>>>(out1_w, out1_b, out2_w, out2_b, d_out);
}